// round 1
// baseline (speedup 1.0000x reference)
#include <cuda_runtime.h>
#include <math.h>

#define D_HID 2048
#define INTER 1408
#define NGU   (2*INTER)   // 2816
#define NEXP  8
#define TMAX  4096
#define TPAIR (TMAX*2)    // 8192

// ---------------- scratch (device globals; no allocation allowed) ------------
__device__ int   g_count[NEXP];
__device__ int   g_tok [NEXP*TMAX];          // token id per (expert, pos)
__device__ int   g_pair[NEXP*TMAX];          // pair index (2t or 2t+1)
__device__ float g_wt  [TPAIR];              // renormalized routing weight per pair
__device__ float g_gu  [(size_t)TPAIR*NGU];  // gate_up GEMM output   (92 MB)
__device__ float g_h   [(size_t)TPAIR*INTER];// swiglu output         (46 MB)
__device__ float g_ct  [(size_t)TPAIR*D_HID];// down GEMM output      (67 MB)

// ---------------- init ----------------
__global__ void zero_counts_kernel() {
    if (threadIdx.x < NEXP) g_count[threadIdx.x] = 0;
}

// ---------------- router: logits -> top2 -> renorm -> scatter ----------------
__global__ void router_kernel(const float* __restrict__ x,
                              const float* __restrict__ rw) {
    int t = blockIdx.x;
    const float* xr = x + (size_t)t * D_HID;
    float p[NEXP];
#pragma unroll
    for (int e = 0; e < NEXP; e++) p[e] = 0.f;
    for (int d = threadIdx.x; d < D_HID; d += blockDim.x) {
        float xv = xr[d];
#pragma unroll
        for (int e = 0; e < NEXP; e++)
            p[e] = fmaf(xv, rw[e * D_HID + d], p[e]);
    }
#pragma unroll
    for (int off = 16; off > 0; off >>= 1) {
#pragma unroll
        for (int e = 0; e < NEXP; e++)
            p[e] += __shfl_down_sync(0xffffffffu, p[e], off);
    }
    __shared__ float s[8][NEXP];
    int warp = threadIdx.x >> 5;
    if ((threadIdx.x & 31) == 0) {
#pragma unroll
        for (int e = 0; e < NEXP; e++) s[warp][e] = p[e];
    }
    __syncthreads();
    if (threadIdx.x == 0) {
        float l[NEXP];
#pragma unroll
        for (int e = 0; e < NEXP; e++) {
            float a = 0.f;
#pragma unroll
            for (int w = 0; w < 8; w++) a += s[w][e];
            l[e] = a;
        }
        // top-2 (first-index wins on ties, matching jax.lax.top_k)
        int i0 = 0;
#pragma unroll
        for (int e = 1; e < NEXP; e++) if (l[e] > l[i0]) i0 = e;
        int i1 = (i0 == 0) ? 1 : 0;
#pragma unroll
        for (int e = 0; e < NEXP; e++)
            if (e != i0 && l[e] > l[i1]) i1 = e;
        // renormalized top-2 softmax weights: softmax denom cancels
        float e1  = expf(l[i1] - l[i0]);
        float inv = 1.f / (1.f + e1);
        g_wt[2*t]     = inv;
        g_wt[2*t + 1] = e1 * inv;
        int p0 = atomicAdd(&g_count[i0], 1);
        g_tok [i0*TMAX + p0] = t;
        g_pair[i0*TMAX + p0] = 2*t;
        int p1 = atomicAdd(&g_count[i1], 1);
        g_tok [i1*TMAX + p1] = t;
        g_pair[i1*TMAX + p1] = 2*t + 1;
    }
}

// ---------------- gathered SGEMM: C[rowC] = A[rowA] @ B_e^T ------------------
// PHASE 0: A = x (param), rowsA = g_tok,  C = g_gu
// PHASE 1: A = g_h,       rowsA = g_pair, C = g_ct
// B is [N, Kd] row-major per expert (ldb == Kd). rowsC = g_pair.
template <int PHASE>
__global__ void __launch_bounds__(256, 2)
gemm_gather_kernel(const float* __restrict__ Aparam,
                   const float* __restrict__ B,
                   int N, int Kd, int lda, int ldc) {
    const float* A      = (PHASE == 0) ? Aparam : g_h;
    float*       C      = (PHASE == 0) ? g_gu   : g_ct;
    const int*   rowsA  = (PHASE == 0) ? g_tok  : g_pair;
    const int*   rowsC  = g_pair;

    int e  = blockIdx.z;
    int M  = g_count[e];
    int m0 = blockIdx.y * 128;
    if (m0 >= M) return;
    int n0 = blockIdx.x * 128;

    const float* Bp = B + (size_t)e * N * Kd;
    const int* rA = rowsA + e * TMAX;
    const int* rC = rowsC + e * TMAX;

    __shared__ float As[16][132];
    __shared__ float Bs[16][132];

    int tid = threadIdx.x;
    int lr  = tid >> 2;          // 0..63
    int lc  = (tid & 3) << 2;    // 0,4,8,12

    int am0 = m0 + lr, am1 = m0 + lr + 64;
    bool v0 = am0 < M, v1 = am1 < M;
    const float* pa0 = A + (size_t)(v0 ? rA[am0] : rA[0]) * lda + lc;
    const float* pa1 = A + (size_t)(v1 ? rA[am1] : rA[0]) * lda + lc;
    const float* pb0 = Bp + (size_t)(n0 + lr)      * Kd + lc;
    const float* pb1 = Bp + (size_t)(n0 + lr + 64) * Kd + lc;

    int ty = tid >> 4, tx = tid & 15;
    float acc[8][8];
#pragma unroll
    for (int i = 0; i < 8; i++)
#pragma unroll
        for (int j = 0; j < 8; j++) acc[i][j] = 0.f;

    for (int k0 = 0; k0 < Kd; k0 += 16) {
        float4 a0 = v0 ? *(const float4*)(pa0 + k0) : make_float4(0,0,0,0);
        float4 a1 = v1 ? *(const float4*)(pa1 + k0) : make_float4(0,0,0,0);
        float4 b0 = *(const float4*)(pb0 + k0);
        float4 b1 = *(const float4*)(pb1 + k0);
        As[lc+0][lr]    = a0.x; As[lc+1][lr]    = a0.y;
        As[lc+2][lr]    = a0.z; As[lc+3][lr]    = a0.w;
        As[lc+0][lr+64] = a1.x; As[lc+1][lr+64] = a1.y;
        As[lc+2][lr+64] = a1.z; As[lc+3][lr+64] = a1.w;
        Bs[lc+0][lr]    = b0.x; Bs[lc+1][lr]    = b0.y;
        Bs[lc+2][lr]    = b0.z; Bs[lc+3][lr]    = b0.w;
        Bs[lc+0][lr+64] = b1.x; Bs[lc+1][lr+64] = b1.y;
        Bs[lc+2][lr+64] = b1.z; Bs[lc+3][lr+64] = b1.w;
        __syncthreads();
#pragma unroll
        for (int kk = 0; kk < 16; kk++) {
            float a[8], b[8];
            *(float4*)(a)     = *(const float4*)&As[kk][ty*8];
            *(float4*)(a + 4) = *(const float4*)&As[kk][ty*8 + 4];
            *(float4*)(b)     = *(const float4*)&Bs[kk][tx*8];
            *(float4*)(b + 4) = *(const float4*)&Bs[kk][tx*8 + 4];
#pragma unroll
            for (int i = 0; i < 8; i++)
#pragma unroll
                for (int j = 0; j < 8; j++)
                    acc[i][j] = fmaf(a[i], b[j], acc[i][j]);
        }
        __syncthreads();
    }

#pragma unroll
    for (int i = 0; i < 8; i++) {
        int gm = m0 + ty*8 + i;
        if (gm < M) {
            float* cr = C + (size_t)rC[gm] * ldc + n0 + tx*8;
            *(float4*)(cr)     = make_float4(acc[i][0], acc[i][1], acc[i][2], acc[i][3]);
            *(float4*)(cr + 4) = make_float4(acc[i][4], acc[i][5], acc[i][6], acc[i][7]);
        }
    }
}

// ---------------- swiglu: h = silu(gate) * up ----------------
__global__ void swiglu_kernel(int total4) {
    int i = blockIdx.x * blockDim.x + threadIdx.x;
    if (i >= total4) return;
    int c = i % (INTER/4);
    int p = i / (INTER/4);
    const float4* gur = (const float4*)(g_gu + (size_t)p * NGU);
    float4 g = gur[c];
    float4 u = gur[c + INTER/4];
    float4 h;
    h.x = (g.x / (1.f + expf(-g.x))) * u.x;
    h.y = (g.y / (1.f + expf(-g.y))) * u.y;
    h.z = (g.z / (1.f + expf(-g.z))) * u.z;
    h.w = (g.w / (1.f + expf(-g.w))) * u.w;
    ((float4*)(g_h + (size_t)p * INTER))[c] = h;
}

// ---------------- combine: out[t] = w0*ct[2t] + w1*ct[2t+1] ------------------
__global__ void combine_kernel(float* __restrict__ out, int total4) {
    int i = blockIdx.x * blockDim.x + threadIdx.x;
    if (i >= total4) return;
    int c = i % (D_HID/4);
    int t = i / (D_HID/4);
    float w0 = g_wt[2*t], w1 = g_wt[2*t + 1];
    float4 c0 = ((const float4*)(g_ct + (size_t)(2*t)     * D_HID))[c];
    float4 c1 = ((const float4*)(g_ct + (size_t)(2*t + 1) * D_HID))[c];
    float4 o;
    o.x = fmaf(w0, c0.x, w1 * c1.x);
    o.y = fmaf(w0, c0.y, w1 * c1.y);
    o.z = fmaf(w0, c0.z, w1 * c1.z);
    o.w = fmaf(w0, c0.w, w1 * c1.w);
    ((float4*)out)[i] = o;
}

// ---------------- launch ----------------
extern "C" void kernel_launch(void* const* d_in, const int* in_sizes, int n_in,
                              void* d_out, int out_size) {
    const float* x   = (const float*)d_in[0];   // [2,2048,2048] -> [4096, 2048]
    const float* rw  = (const float*)d_in[1];   // [8, 2048]
    const float* gup = (const float*)d_in[2];   // [8, 2816, 2048]
    const float* dwn = (const float*)d_in[3];   // [8, 2048, 1408]
    float* out = (float*)d_out;
    int T = in_sizes[0] / D_HID;                // 4096

    zero_counts_kernel<<<1, 32>>>();
    router_kernel<<<T, 256>>>(x, rw);

    dim3 g0(NGU / 128, (T + 127) / 128, NEXP);  // (22, 32, 8)
    gemm_gather_kernel<0><<<g0, 256>>>(x, gup, NGU, D_HID, D_HID, NGU);

    int sw_total4 = TPAIR * (INTER / 4);
    swiglu_kernel<<<(sw_total4 + 255) / 256, 256>>>(sw_total4);

    dim3 g1(D_HID / 128, (T + 127) / 128, NEXP); // (16, 32, 8)
    gemm_gather_kernel<1><<<g1, 256>>>(x /*unused*/, dwn, D_HID, INTER, INTER, D_HID);

    int cb_total4 = T * (D_HID / 4);
    combine_kernel<<<(cb_total4 + 255) / 256, 256>>>(out, cb_total4);
}

// round 3
// speedup vs baseline: 2.1673x; 2.1673x over previous
#include <cuda_runtime.h>
#include <cuda_bf16.h>
#include <cstdint>
#include <math.h>

#define D_HID 2048
#define INTER 1408
#define NGU   2816
#define NEXP  8
#define TMAX  4096
#define TPAIR 8192
#define RMAX  9216   // 8192 + 8*128 padding for 128-aligned expert regions

// ---------------- device scratch ----------------
__device__ int   g_count[NEXP];
__device__ int   g_off[NEXP];
__device__ int   g_top_e[TPAIR];
__device__ int   g_pos[TPAIR];
__device__ int   g_p2s[TPAIR];
__device__ float g_wt[TPAIR];
__device__ __align__(256) __nv_bfloat16 g_xg_hi [(size_t)RMAX * D_HID];
__device__ __align__(256) __nv_bfloat16 g_xg_lo [(size_t)RMAX * D_HID];
__device__ __align__(256) __nv_bfloat16 g_gup_hi[(size_t)NEXP * NGU * D_HID];
__device__ __align__(256) __nv_bfloat16 g_gup_lo[(size_t)NEXP * NGU * D_HID];
__device__ __align__(256) __nv_bfloat16 g_dwn_hi[(size_t)NEXP * D_HID * INTER];
__device__ __align__(256) __nv_bfloat16 g_dwn_lo[(size_t)NEXP * D_HID * INTER];
__device__ __align__(256) __nv_bfloat16 g_h_hi  [(size_t)RMAX * INTER];
__device__ __align__(256) __nv_bfloat16 g_h_lo  [(size_t)RMAX * INTER];
__device__ __align__(256) float         g_gu    [(size_t)RMAX * NGU];
__device__ __align__(256) float         g_ct    [(size_t)RMAX * D_HID];

// ---------------- helpers ----------------
__device__ __forceinline__ uint32_t smem_u32(const void* p) {
    uint32_t a;
    asm("{ .reg .u64 t; cvta.to.shared.u64 t, %1; cvt.u32.u64 %0, t; }" : "=r"(a) : "l"(p));
    return a;
}

__device__ __forceinline__ void cp16z(uint32_t dst, const void* src, uint32_t sz) {
    asm volatile("cp.async.cg.shared.global [%0], [%1], 16, %2;"
                 :: "r"(dst), "l"(src), "r"(sz));
}

__device__ __forceinline__ void ldsm4(uint32_t* r, uint32_t addr) {
    asm volatile("ldmatrix.sync.aligned.m8n8.x4.shared.b16 {%0,%1,%2,%3}, [%4];"
                 : "=r"(r[0]), "=r"(r[1]), "=r"(r[2]), "=r"(r[3]) : "r"(addr));
}

__device__ __forceinline__ void mma_bf16(float* d, const uint32_t* a, const uint32_t* b) {
    asm volatile("mma.sync.aligned.m16n8k16.row.col.f32.bf16.bf16.f32 "
                 "{%0,%1,%2,%3}, {%4,%5,%6,%7}, {%8,%9}, {%0,%1,%2,%3};"
                 : "+f"(d[0]), "+f"(d[1]), "+f"(d[2]), "+f"(d[3])
                 : "r"(a[0]), "r"(a[1]), "r"(a[2]), "r"(a[3]), "r"(b[0]), "r"(b[1]));
}

__device__ __forceinline__ void f2bf2(float x, __nv_bfloat16& hi, __nv_bfloat16& lo) {
    hi = __float2bfloat16(x);
    lo = __float2bfloat16(x - __bfloat162float(hi));
}

// ---------------- init ----------------
__global__ void zero_counts_kernel() {
    if (threadIdx.x < NEXP) g_count[threadIdx.x] = 0;
}

// ---------------- router ----------------
__global__ void router_kernel(const float* __restrict__ x,
                              const float* __restrict__ rw) {
    int t = blockIdx.x;
    const float* xr = x + (size_t)t * D_HID;
    float p[NEXP];
#pragma unroll
    for (int e = 0; e < NEXP; e++) p[e] = 0.f;
    for (int d = threadIdx.x; d < D_HID; d += blockDim.x) {
        float xv = xr[d];
#pragma unroll
        for (int e = 0; e < NEXP; e++)
            p[e] = fmaf(xv, rw[e * D_HID + d], p[e]);
    }
#pragma unroll
    for (int off = 16; off > 0; off >>= 1)
#pragma unroll
        for (int e = 0; e < NEXP; e++)
            p[e] += __shfl_down_sync(0xffffffffu, p[e], off);
    __shared__ float s[8][NEXP];
    int warp = threadIdx.x >> 5;
    if ((threadIdx.x & 31) == 0)
#pragma unroll
        for (int e = 0; e < NEXP; e++) s[warp][e] = p[e];
    __syncthreads();
    if (threadIdx.x == 0) {
        float l[NEXP];
#pragma unroll
        for (int e = 0; e < NEXP; e++) {
            float a = 0.f;
#pragma unroll
            for (int w = 0; w < 8; w++) a += s[w][e];
            l[e] = a;
        }
        int i0 = 0;
#pragma unroll
        for (int e = 1; e < NEXP; e++) if (l[e] > l[i0]) i0 = e;
        int i1 = (i0 == 0) ? 1 : 0;
#pragma unroll
        for (int e = 0; e < NEXP; e++)
            if (e != i0 && l[e] > l[i1]) i1 = e;
        float e1  = expf(l[i1] - l[i0]);
        float inv = 1.f / (1.f + e1);
        g_wt[2*t]   = inv;
        g_wt[2*t+1] = e1 * inv;
        int p0 = atomicAdd(&g_count[i0], 1);
        g_top_e[2*t] = i0; g_pos[2*t] = p0;
        int p1 = atomicAdd(&g_count[i1], 1);
        g_top_e[2*t+1] = i1; g_pos[2*t+1] = p1;
    }
}

__global__ void offsets_kernel() {
    if (threadIdx.x == 0) {
        int o = 0;
        for (int e = 0; e < NEXP; e++) {
            g_off[e] = o;
            o += (g_count[e] + 127) & ~127;
        }
    }
}

__global__ void map_kernel() {
    int p = blockIdx.x * blockDim.x + threadIdx.x;
    if (p < TPAIR)
        g_p2s[p] = g_off[g_top_e[p]] + g_pos[p];
}

// gather x rows into slot order, bf16 hi/lo split
__global__ void gather_x_kernel(const float* __restrict__ x) {
    int p = blockIdx.x;
    int t = p >> 1;
    int s = g_p2s[p];
    const float4* src = (const float4*)(x + (size_t)t * D_HID);
    __nv_bfloat162* dh = (__nv_bfloat162*)(g_xg_hi + (size_t)s * D_HID);
    __nv_bfloat162* dl = (__nv_bfloat162*)(g_xg_lo + (size_t)s * D_HID);
    for (int i = threadIdx.x; i < D_HID/4; i += blockDim.x) {
        float4 v = src[i];
        __nv_bfloat16 h0,l0,h1,l1,h2,l2,h3,l3;
        f2bf2(v.x,h0,l0); f2bf2(v.y,h1,l1); f2bf2(v.z,h2,l2); f2bf2(v.w,h3,l3);
        __nv_bfloat162 a; a.x = h0; a.y = h1;
        __nv_bfloat162 b; b.x = h2; b.y = h3;
        dh[2*i] = a; dh[2*i+1] = b;
        a.x = l0; a.y = l1; b.x = l2; b.y = l3;
        dl[2*i] = a; dl[2*i+1] = b;
    }
}

__global__ void conv_gup_kernel(const float* __restrict__ w) {
    int row = blockIdx.x;            // 0..NEXP*NGU-1
    const float4* src = (const float4*)(w + (size_t)row * D_HID);
    __nv_bfloat162* dh = (__nv_bfloat162*)(g_gup_hi + (size_t)row * D_HID);
    __nv_bfloat162* dl = (__nv_bfloat162*)(g_gup_lo + (size_t)row * D_HID);
    for (int i = threadIdx.x; i < D_HID/4; i += blockDim.x) {
        float4 v = src[i];
        __nv_bfloat16 h0,l0,h1,l1,h2,l2,h3,l3;
        f2bf2(v.x,h0,l0); f2bf2(v.y,h1,l1); f2bf2(v.z,h2,l2); f2bf2(v.w,h3,l3);
        __nv_bfloat162 a; a.x = h0; a.y = h1;
        __nv_bfloat162 c; c.x = h2; c.y = h3;
        dh[2*i] = a; dh[2*i+1] = c;
        a.x = l0; a.y = l1; c.x = l2; c.y = l3;
        dl[2*i] = a; dl[2*i+1] = c;
    }
}

__global__ void conv_dwn_kernel(const float* __restrict__ w) {
    int row = blockIdx.x;            // 0..NEXP*D_HID-1
    const float4* src = (const float4*)(w + (size_t)row * INTER);
    __nv_bfloat162* dh = (__nv_bfloat162*)(g_dwn_hi + (size_t)row * INTER);
    __nv_bfloat162* dl = (__nv_bfloat162*)(g_dwn_lo + (size_t)row * INTER);
    for (int i = threadIdx.x; i < INTER/4; i += blockDim.x) {
        float4 v = src[i];
        __nv_bfloat16 h0,l0,h1,l1,h2,l2,h3,l3;
        f2bf2(v.x,h0,l0); f2bf2(v.y,h1,l1); f2bf2(v.z,h2,l2); f2bf2(v.w,h3,l3);
        __nv_bfloat162 a; a.x = h0; a.y = h1;
        __nv_bfloat162 c; c.x = h2; c.y = h3;
        dh[2*i] = a; dh[2*i+1] = c;
        a.x = l0; a.y = l1; c.x = l2; c.y = l3;
        dl[2*i] = a; dl[2*i+1] = c;
    }
}

// ---------------- HMMA grouped GEMM (bf16x3 split) ----------------
// CTA tile 128x128, warp tile 32x64 (8 warps: 4 in M x 2 in N)
// smem: per stage, 4 tiles (Ahi, Alo, Bhi, Blo), each 128 rows x 80B pitch
#define PITCH 80
#define TILE_BYTES (128*PITCH)       // 10240
#define AH_OFF 0
#define AL_OFF TILE_BYTES
#define BH_OFF (2*TILE_BYTES)
#define BL_OFF (3*TILE_BYTES)
#define STAGE  (4*TILE_BYTES)        // 40960
#define NSTG   4
#define GEMM_SMEM (NSTG*STAGE)       // 163840

template <int PHASE>
__global__ void __launch_bounds__(256, 1)
moe_gemm_kernel() {
    constexpr int Kd   = (PHASE == 0) ? D_HID : INTER;   // 2048 / 1408
    constexpr int NCH  = Kd / 32;                        // 64 / 44

    int e   = blockIdx.z;
    int cnt = g_count[e];
    int m0  = blockIdx.x * 128;
    if (m0 >= cnt) return;
    int n0  = blockIdx.y * 128;
    int off_e = g_off[e];

    const __nv_bfloat16* Ahi = ((PHASE == 0) ? g_xg_hi : g_h_hi) + (size_t)(off_e + m0) * Kd;
    const __nv_bfloat16* Alo = ((PHASE == 0) ? g_xg_lo : g_h_lo) + (size_t)(off_e + m0) * Kd;
    const __nv_bfloat16* Bhi = ((PHASE == 0) ? g_gup_hi : g_dwn_hi) +
                               ((size_t)e * ((PHASE == 0) ? NGU : D_HID) + n0) * Kd;
    const __nv_bfloat16* Blo = ((PHASE == 0) ? g_gup_lo : g_dwn_lo) +
                               ((size_t)e * ((PHASE == 0) ? NGU : D_HID) + n0) * Kd;

    extern __shared__ __align__(128) char smem[];
    uint32_t sb = smem_u32(smem);

    int tid = threadIdx.x;
    int wid = tid >> 5;
    int lid = tid & 31;
    int warp_m = (wid >> 1) * 32;
    int warp_n = (wid & 1) * 64;

    // ---- per-thread cp.async assignments (2 x 16B per tile per chunk) ----
    int c0 = tid, c1 = tid + 256;
    int r0 = c0 >> 2, q0 = c0 & 3;
    int r1 = c1 >> 2, q1 = c1 & 3;
    uint32_t so0 = (uint32_t)(r0 * PITCH + q0 * 16);
    uint32_t so1 = (uint32_t)(r1 * PITCH + q1 * 16);
    const char* pAh0 = (const char*)(Ahi + (size_t)r0 * Kd + q0 * 8);
    const char* pAh1 = (const char*)(Ahi + (size_t)r1 * Kd + q1 * 8);
    const char* pAl0 = (const char*)(Alo + (size_t)r0 * Kd + q0 * 8);
    const char* pAl1 = (const char*)(Alo + (size_t)r1 * Kd + q1 * 8);
    const char* pBh0 = (const char*)(Bhi + (size_t)r0 * Kd + q0 * 8);
    const char* pBh1 = (const char*)(Bhi + (size_t)r1 * Kd + q1 * 8);
    const char* pBl0 = (const char*)(Blo + (size_t)r0 * Kd + q0 * 8);
    const char* pBl1 = (const char*)(Blo + (size_t)r1 * Kd + q1 * 8);
    uint32_t szA0 = (m0 + r0 < cnt) ? 16u : 0u;
    uint32_t szA1 = (m0 + r1 < cnt) ? 16u : 0u;

    // ---- ldmatrix per-lane offsets ----
    // A (x4): lanes 0-7 rows0-7 k0, 8-15 rows8-15 k0, 16-23 rows0-7 +16B, 24-31 rows8-15 +16B
    uint32_t a_off = (uint32_t)((warp_m + (lid & 15)) * PITCH + (lid >> 4) * 16);
    // B (x4): lanes 0-7 n0-7 k0, 8-15 n0-7 +16B, 16-23 n8-15 k0, 24-31 n8-15 +16B
    uint32_t b_off = (uint32_t)((warp_n + (lid & 7) + ((lid & 16) >> 1)) * PITCH +
                                ((lid >> 3) & 1) * 16);

    float d[2][8][4];
#pragma unroll
    for (int mi = 0; mi < 2; mi++)
#pragma unroll
        for (int ni = 0; ni < 8; ni++)
#pragma unroll
            for (int k = 0; k < 4; k++) d[mi][ni][k] = 0.f;

    auto load_chunk = [&](int ci, int s) {
        uint32_t st = sb + s * STAGE;
        size_t go = (size_t)ci * 64;   // 32 bf16 = 64 bytes along K
        cp16z(st + AH_OFF + so0, pAh0 + go, szA0);
        cp16z(st + AH_OFF + so1, pAh1 + go, szA1);
        cp16z(st + AL_OFF + so0, pAl0 + go, szA0);
        cp16z(st + AL_OFF + so1, pAl1 + go, szA1);
        cp16z(st + BH_OFF + so0, pBh0 + go, 16u);
        cp16z(st + BH_OFF + so1, pBh1 + go, 16u);
        cp16z(st + BL_OFF + so0, pBl0 + go, 16u);
        cp16z(st + BL_OFF + so1, pBl1 + go, 16u);
    };

    // prologue: stages 0..2
#pragma unroll
    for (int s = 0; s < NSTG - 1; s++) {
        load_chunk(s, s);
        asm volatile("cp.async.commit_group;" ::: "memory");
    }

#pragma unroll 1
    for (int i = 0; i < NCH; i++) {
        asm volatile("cp.async.wait_group 2;" ::: "memory");
        __syncthreads();
        int nxt = i + NSTG - 1;
        if (nxt < NCH) load_chunk(nxt, nxt & (NSTG - 1));
        asm volatile("cp.async.commit_group;" ::: "memory");

        uint32_t st = sb + (i & (NSTG - 1)) * STAGE;
#pragma unroll
        for (int kk = 0; kk < 2; kk++) {
            uint32_t ko = kk * 32;
            uint32_t ah[2][4], al[2][4], bh[4][4], bl[4][4];
            ldsm4(ah[0], st + AH_OFF + a_off + ko);
            ldsm4(ah[1], st + AH_OFF + a_off + ko + 16 * PITCH);
            ldsm4(al[0], st + AL_OFF + a_off + ko);
            ldsm4(al[1], st + AL_OFF + a_off + ko + 16 * PITCH);
#pragma unroll
            for (int np = 0; np < 4; np++) {
                ldsm4(bh[np], st + BH_OFF + b_off + ko + np * 16 * PITCH);
                ldsm4(bl[np], st + BL_OFF + b_off + ko + np * 16 * PITCH);
            }
#pragma unroll
            for (int mi = 0; mi < 2; mi++)
#pragma unroll
                for (int ni = 0; ni < 8; ni++) {
                    const uint32_t* bph = &bh[ni >> 1][(ni & 1) * 2];
                    const uint32_t* bpl = &bl[ni >> 1][(ni & 1) * 2];
                    mma_bf16(d[mi][ni], ah[mi], bph);
                    mma_bf16(d[mi][ni], ah[mi], bpl);
                    mma_bf16(d[mi][ni], al[mi], bph);
                }
        }
    }

    // ---- epilogue: direct fp32 stores ----
    constexpr int ldc = (PHASE == 0) ? NGU : D_HID;
    float* C = ((PHASE == 0) ? g_gu : g_ct);
#pragma unroll
    for (int mi = 0; mi < 2; mi++) {
        int rA = warp_m + mi * 16 + (lid >> 2);
        int rB = rA + 8;
        bool vA = (m0 + rA) < cnt;
        bool vB = (m0 + rB) < cnt;
        float* cA = C + (size_t)(off_e + m0 + rA) * ldc + n0 + warp_n + (lid & 3) * 2;
        float* cB = C + (size_t)(off_e + m0 + rB) * ldc + n0 + warp_n + (lid & 3) * 2;
#pragma unroll
        for (int ni = 0; ni < 8; ni++) {
            if (vA) { float2 v; v.x = d[mi][ni][0]; v.y = d[mi][ni][1];
                      *(float2*)(cA + ni * 8) = v; }
            if (vB) { float2 v; v.x = d[mi][ni][2]; v.y = d[mi][ni][3];
                      *(float2*)(cB + ni * 8) = v; }
        }
    }
}

// ---------------- swiglu: g_gu -> g_h hi/lo ----------------
__global__ void swiglu_kernel() {
    int p = blockIdx.x;
    int s = g_p2s[p];
    const float4* gg = (const float4*)(g_gu + (size_t)s * NGU);
    const float4* uu = (const float4*)(g_gu + (size_t)s * NGU + INTER);
    __nv_bfloat162* dh = (__nv_bfloat162*)(g_h_hi + (size_t)s * INTER);
    __nv_bfloat162* dl = (__nv_bfloat162*)(g_h_lo + (size_t)s * INTER);
    for (int i = threadIdx.x; i < INTER/4; i += blockDim.x) {
        float4 g = gg[i];
        float4 u = uu[i];
        float4 h;
        h.x = g.x / (1.f + expf(-g.x)) * u.x;
        h.y = g.y / (1.f + expf(-g.y)) * u.y;
        h.z = g.z / (1.f + expf(-g.z)) * u.z;
        h.w = g.w / (1.f + expf(-g.w)) * u.w;
        __nv_bfloat16 h0,l0,h1,l1,h2,l2,h3,l3;
        f2bf2(h.x,h0,l0); f2bf2(h.y,h1,l1); f2bf2(h.z,h2,l2); f2bf2(h.w,h3,l3);
        __nv_bfloat162 a; a.x = h0; a.y = h1;
        __nv_bfloat162 b; b.x = h2; b.y = h3;
        dh[2*i] = a; dh[2*i+1] = b;
        a.x = l0; a.y = l1; b.x = l2; b.y = l3;
        dl[2*i] = a; dl[2*i+1] = b;
    }
}

// ---------------- combine ----------------
__global__ void combine_kernel(float* __restrict__ out, int total4) {
    int i = blockIdx.x * blockDim.x + threadIdx.x;
    if (i >= total4) return;
    int c = i % (D_HID/4);
    int t = i / (D_HID/4);
    float w0 = g_wt[2*t], w1 = g_wt[2*t+1];
    int s0 = g_p2s[2*t], s1 = g_p2s[2*t+1];
    float4 c0 = ((const float4*)(g_ct + (size_t)s0 * D_HID))[c];
    float4 c1 = ((const float4*)(g_ct + (size_t)s1 * D_HID))[c];
    float4 o;
    o.x = fmaf(w0, c0.x, w1 * c1.x);
    o.y = fmaf(w0, c0.y, w1 * c1.y);
    o.z = fmaf(w0, c0.z, w1 * c1.z);
    o.w = fmaf(w0, c0.w, w1 * c1.w);
    ((float4*)out)[i] = o;
}

// ---------------- launch ----------------
extern "C" void kernel_launch(void* const* d_in, const int* in_sizes, int n_in,
                              void* d_out, int out_size) {
    const float* x   = (const float*)d_in[0];
    const float* rw  = (const float*)d_in[1];
    const float* gup = (const float*)d_in[2];
    const float* dwn = (const float*)d_in[3];
    float* out = (float*)d_out;
    int T = in_sizes[0] / D_HID;   // 4096

    cudaFuncSetAttribute(moe_gemm_kernel<0>, cudaFuncAttributeMaxDynamicSharedMemorySize, GEMM_SMEM);
    cudaFuncSetAttribute(moe_gemm_kernel<1>, cudaFuncAttributeMaxDynamicSharedMemorySize, GEMM_SMEM);

    zero_counts_kernel<<<1, 32>>>();
    router_kernel<<<T, 256>>>(x, rw);
    offsets_kernel<<<1, 1>>>();
    map_kernel<<<(TPAIR + 255) / 256, 256>>>();
    gather_x_kernel<<<TPAIR, 128>>>(x);
    conv_gup_kernel<<<NEXP * NGU, 128>>>(gup);
    conv_dwn_kernel<<<NEXP * D_HID, 128>>>(dwn);

    dim3 g0(32, NGU / 128, NEXP);     // (m-tiles, 22, 8)
    moe_gemm_kernel<0><<<g0, 256, GEMM_SMEM>>>();

    swiglu_kernel<<<TPAIR, 128>>>();

    dim3 g1(32, D_HID / 128, NEXP);   // (m-tiles, 16, 8)
    moe_gemm_kernel<1><<<g1, 256, GEMM_SMEM>>>();

    combine_kernel<<<(T * (D_HID/4) + 255) / 256, 256>>>(out, T * (D_HID/4));
}

// round 4
// speedup vs baseline: 2.4763x; 1.1426x over previous
#include <cuda_runtime.h>
#include <cuda_bf16.h>
#include <cstdint>
#include <math.h>

#define D_HID 2048
#define INTER 1408
#define NGU   2816
#define NEXP  8
#define TMAX  4096
#define TPAIR 8192
#define RMAX  9216

// ---------------- device scratch ----------------
__device__ int   g_count[NEXP];
__device__ int   g_top_e[TPAIR];
__device__ int   g_pos[TPAIR];
__device__ int   g_p2s[TPAIR];
__device__ float g_wt[TPAIR];
__device__ __align__(256) __nv_bfloat16 g_xg_hi [(size_t)RMAX * D_HID];
__device__ __align__(256) __nv_bfloat16 g_xg_lo [(size_t)RMAX * D_HID];
__device__ __align__(256) __nv_bfloat16 g_gup_hi[(size_t)NEXP * NGU * D_HID];
__device__ __align__(256) __nv_bfloat16 g_gup_lo[(size_t)NEXP * NGU * D_HID];
__device__ __align__(256) __nv_bfloat16 g_dwn_hi[(size_t)NEXP * D_HID * INTER];
__device__ __align__(256) __nv_bfloat16 g_dwn_lo[(size_t)NEXP * D_HID * INTER];
__device__ __align__(256) __nv_bfloat16 g_h_hi  [(size_t)RMAX * INTER];
__device__ __align__(256) __nv_bfloat16 g_h_lo  [(size_t)RMAX * INTER];
__device__ __align__(256) float         g_ct    [(size_t)RMAX * D_HID];

// ---------------- helpers ----------------
__device__ __forceinline__ uint32_t smem_u32(const void* p) {
    uint32_t a;
    asm("{ .reg .u64 t; cvta.to.shared.u64 t, %1; cvt.u32.u64 %0, t; }" : "=r"(a) : "l"(p));
    return a;
}
__device__ __forceinline__ void cp16z(uint32_t dst, const void* src, uint32_t sz) {
    asm volatile("cp.async.cg.shared.global [%0], [%1], 16, %2;"
                 :: "r"(dst), "l"(src), "r"(sz));
}
__device__ __forceinline__ void ldsm4(uint32_t* r, uint32_t addr) {
    asm volatile("ldmatrix.sync.aligned.m8n8.x4.shared.b16 {%0,%1,%2,%3}, [%4];"
                 : "=r"(r[0]), "=r"(r[1]), "=r"(r[2]), "=r"(r[3]) : "r"(addr));
}
__device__ __forceinline__ void mma_bf16(float* d, const uint32_t* a, const uint32_t* b) {
    asm volatile("mma.sync.aligned.m16n8k16.row.col.f32.bf16.bf16.f32 "
                 "{%0,%1,%2,%3}, {%4,%5,%6,%7}, {%8,%9}, {%0,%1,%2,%3};"
                 : "+f"(d[0]), "+f"(d[1]), "+f"(d[2]), "+f"(d[3])
                 : "r"(a[0]), "r"(a[1]), "r"(a[2]), "r"(a[3]), "r"(b[0]), "r"(b[1]));
}
__device__ __forceinline__ void f2bf2(float x, __nv_bfloat16& hi, __nv_bfloat16& lo) {
    hi = __float2bfloat16(x);
    lo = __float2bfloat16(x - __bfloat162float(hi));
}
__device__ __forceinline__ int expert_base(int e) {
    int o = 0;
#pragma unroll
    for (int k = 0; k < NEXP; k++)
        if (k < e) o += (g_count[k] + 127) & ~127;
    return o;
}

// ---------------- init ----------------
__global__ void zero_counts_kernel() {
    if (threadIdx.x < NEXP) g_count[threadIdx.x] = 0;
}

// ---------------- router ----------------
__global__ void router_kernel(const float* __restrict__ x,
                              const float* __restrict__ rw) {
    int t = blockIdx.x;
    const float* xr = x + (size_t)t * D_HID;
    float p[NEXP];
#pragma unroll
    for (int e = 0; e < NEXP; e++) p[e] = 0.f;
    for (int d = threadIdx.x; d < D_HID; d += blockDim.x) {
        float xv = xr[d];
#pragma unroll
        for (int e = 0; e < NEXP; e++)
            p[e] = fmaf(xv, rw[e * D_HID + d], p[e]);
    }
#pragma unroll
    for (int off = 16; off > 0; off >>= 1)
#pragma unroll
        for (int e = 0; e < NEXP; e++)
            p[e] += __shfl_down_sync(0xffffffffu, p[e], off);
    __shared__ float s[8][NEXP];
    int warp = threadIdx.x >> 5;
    if ((threadIdx.x & 31) == 0)
#pragma unroll
        for (int e = 0; e < NEXP; e++) s[warp][e] = p[e];
    __syncthreads();
    if (threadIdx.x == 0) {
        float l[NEXP];
#pragma unroll
        for (int e = 0; e < NEXP; e++) {
            float a = 0.f;
#pragma unroll
            for (int w = 0; w < 8; w++) a += s[w][e];
            l[e] = a;
        }
        int i0 = 0;
#pragma unroll
        for (int e = 1; e < NEXP; e++) if (l[e] > l[i0]) i0 = e;
        int i1 = (i0 == 0) ? 1 : 0;
#pragma unroll
        for (int e = 0; e < NEXP; e++)
            if (e != i0 && l[e] > l[i1]) i1 = e;
        float e1  = expf(l[i1] - l[i0]);
        float inv = 1.f / (1.f + e1);
        g_wt[2*t]   = inv;
        g_wt[2*t+1] = e1 * inv;
        int p0 = atomicAdd(&g_count[i0], 1);
        g_top_e[2*t] = i0; g_pos[2*t] = p0;
        int p1 = atomicAdd(&g_count[i1], 1);
        g_top_e[2*t+1] = i1; g_pos[2*t+1] = p1;
    }
}

// ---------------- prep: gather-x + weight conversions (one kernel) ----------
// blocks [0, TPAIR): gather token rows -> slot order, hi/lo split
// blocks [TPAIR, TPAIR+NEXP*NGU): gate_up conversion (32-col interleave)
// rest: down conversion
__global__ void prep_kernel(const float* __restrict__ x,
                            const float* __restrict__ gup,
                            const float* __restrict__ dwn) {
    int b = blockIdx.x;
    if (b < TPAIR) {
        int p = b;
        int t = p >> 1;
        int s = expert_base(g_top_e[p]) + g_pos[p];
        if (threadIdx.x == 0) g_p2s[p] = s;
        const float4* src = (const float4*)(x + (size_t)t * D_HID);
        __nv_bfloat162* dh = (__nv_bfloat162*)(g_xg_hi + (size_t)s * D_HID);
        __nv_bfloat162* dl = (__nv_bfloat162*)(g_xg_lo + (size_t)s * D_HID);
        for (int i = threadIdx.x; i < D_HID/4; i += blockDim.x) {
            float4 v = src[i];
            __nv_bfloat16 h0,l0,h1,l1,h2,l2,h3,l3;
            f2bf2(v.x,h0,l0); f2bf2(v.y,h1,l1); f2bf2(v.z,h2,l2); f2bf2(v.w,h3,l3);
            __nv_bfloat162 a; a.x = h0; a.y = h1;
            __nv_bfloat162 c; c.x = h2; c.y = h3;
            dh[2*i] = a; dh[2*i+1] = c;
            a.x = l0; a.y = l1; c.x = l2; c.y = l3;
            dl[2*i] = a; dl[2*i+1] = c;
        }
    } else if (b < TPAIR + NEXP * NGU) {
        int row = b - TPAIR;                 // dest row
        int e = row / NGU;
        int n = row % NGU;
        int blk = n >> 6, r = n & 63;
        int src_n = (r < 32) ? (blk*32 + r) : (INTER + blk*32 + (r - 32));
        const float4* src = (const float4*)(gup + ((size_t)e * NGU + src_n) * D_HID);
        __nv_bfloat162* dh = (__nv_bfloat162*)(g_gup_hi + (size_t)row * D_HID);
        __nv_bfloat162* dl = (__nv_bfloat162*)(g_gup_lo + (size_t)row * D_HID);
        for (int i = threadIdx.x; i < D_HID/4; i += blockDim.x) {
            float4 v = src[i];
            __nv_bfloat16 h0,l0,h1,l1,h2,l2,h3,l3;
            f2bf2(v.x,h0,l0); f2bf2(v.y,h1,l1); f2bf2(v.z,h2,l2); f2bf2(v.w,h3,l3);
            __nv_bfloat162 a; a.x = h0; a.y = h1;
            __nv_bfloat162 c; c.x = h2; c.y = h3;
            dh[2*i] = a; dh[2*i+1] = c;
            a.x = l0; a.y = l1; c.x = l2; c.y = l3;
            dl[2*i] = a; dl[2*i+1] = c;
        }
    } else {
        int row = b - TPAIR - NEXP * NGU;    // 0..NEXP*D_HID-1
        const float4* src = (const float4*)(dwn + (size_t)row * INTER);
        __nv_bfloat162* dh = (__nv_bfloat162*)(g_dwn_hi + (size_t)row * INTER);
        __nv_bfloat162* dl = (__nv_bfloat162*)(g_dwn_lo + (size_t)row * INTER);
        for (int i = threadIdx.x; i < INTER/4; i += blockDim.x) {
            float4 v = src[i];
            __nv_bfloat16 h0,l0,h1,l1,h2,l2,h3,l3;
            f2bf2(v.x,h0,l0); f2bf2(v.y,h1,l1); f2bf2(v.z,h2,l2); f2bf2(v.w,h3,l3);
            __nv_bfloat162 a; a.x = h0; a.y = h1;
            __nv_bfloat162 c; c.x = h2; c.y = h3;
            dh[2*i] = a; dh[2*i+1] = c;
            a.x = l0; a.y = l1; c.x = l2; c.y = l3;
            dl[2*i] = a; dl[2*i+1] = c;
        }
    }
}

// ---------------- HMMA grouped GEMM (bf16x3), CTA 128x256, 512 thr ----------
#define PITCH 80
#define A_TILE (128*PITCH)           // 10240
#define B_TILE (256*PITCH)           // 20480
#define AH_OFF 0
#define AL_OFF A_TILE
#define BH_OFF (2*A_TILE)
#define BL_OFF (2*A_TILE + B_TILE)
#define STAGE  (2*A_TILE + 2*B_TILE) // 61440
#define NSTG   3
#define GEMM_SMEM (NSTG*STAGE)       // 184320

template <int PHASE>
__global__ void __launch_bounds__(512, 1)
moe_gemm_kernel() {
    constexpr int Kd  = (PHASE == 0) ? D_HID : INTER;   // 2048 / 1408
    constexpr int NCH = Kd / 32;                        // 64 / 44
    constexpr int NROW = (PHASE == 0) ? NGU : D_HID;

    int e   = blockIdx.z;
    int cnt = g_count[e];
    int m0  = blockIdx.x * 128;
    if (m0 >= cnt) return;
    int n0  = blockIdx.y * 256;
    int off_e = expert_base(e);

    const __nv_bfloat16* Ahi = ((PHASE == 0) ? g_xg_hi : g_h_hi) + (size_t)(off_e + m0) * Kd;
    const __nv_bfloat16* Alo = ((PHASE == 0) ? g_xg_lo : g_h_lo) + (size_t)(off_e + m0) * Kd;
    const __nv_bfloat16* Bhi = ((PHASE == 0) ? g_gup_hi : g_dwn_hi) + ((size_t)e * NROW + n0) * Kd;
    const __nv_bfloat16* Blo = ((PHASE == 0) ? g_gup_lo : g_dwn_lo) + ((size_t)e * NROW + n0) * Kd;

    extern __shared__ __align__(128) char smem[];
    uint32_t sb = smem_u32(smem);

    int tid = threadIdx.x;
    int wid = tid >> 5;
    int lid = tid & 31;
    int warp_m = (wid >> 2) * 32;      // 0,32,64,96
    int warp_n = (wid & 3) * 64;       // 0,64,128,192

    // cp.async assignments: A pair at idx=tid (512 ops each tile),
    // B pairs at idx=tid, tid+512 (1024 ops each tile)
    int ra  = tid >> 2, qa = tid & 3;
    int rb0 = tid >> 2, qb0 = tid & 3;
    int rb1 = (tid + 512) >> 2, qb1 = tid & 3;
    uint32_t soA  = (uint32_t)(ra  * PITCH + qa  * 16);
    uint32_t soB0 = (uint32_t)(rb0 * PITCH + qb0 * 16);
    uint32_t soB1 = (uint32_t)(rb1 * PITCH + qb1 * 16);
    const char* pAh = (const char*)(Ahi + (size_t)ra  * Kd + qa  * 8);
    const char* pAl = (const char*)(Alo + (size_t)ra  * Kd + qa  * 8);
    const char* pBh0 = (const char*)(Bhi + (size_t)rb0 * Kd + qb0 * 8);
    const char* pBl0 = (const char*)(Blo + (size_t)rb0 * Kd + qb0 * 8);
    const char* pBh1 = (const char*)(Bhi + (size_t)rb1 * Kd + qb1 * 8);
    const char* pBl1 = (const char*)(Blo + (size_t)rb1 * Kd + qb1 * 8);
    uint32_t szA = (m0 + ra < cnt) ? 16u : 0u;

    uint32_t a_off = (uint32_t)((warp_m + (lid & 15)) * PITCH + (lid >> 4) * 16);
    uint32_t b_off = (uint32_t)((warp_n + (lid & 7) + ((lid & 16) >> 1)) * PITCH +
                                ((lid >> 3) & 1) * 16);

    float d[2][8][4];
#pragma unroll
    for (int mi = 0; mi < 2; mi++)
#pragma unroll
        for (int ni = 0; ni < 8; ni++)
#pragma unroll
            for (int k = 0; k < 4; k++) d[mi][ni][k] = 0.f;

    auto load_chunk = [&](int ci, int s) {
        uint32_t st = sb + s * STAGE;
        size_t go = (size_t)ci * 64;
        cp16z(st + AH_OFF + soA,  pAh  + go, szA);
        cp16z(st + AL_OFF + soA,  pAl  + go, szA);
        cp16z(st + BH_OFF + soB0, pBh0 + go, 16u);
        cp16z(st + BL_OFF + soB0, pBl0 + go, 16u);
        cp16z(st + BH_OFF + soB1, pBh1 + go, 16u);
        cp16z(st + BL_OFF + soB1, pBl1 + go, 16u);
    };

    load_chunk(0, 0);
    asm volatile("cp.async.commit_group;" ::: "memory");
    load_chunk(1, 1);
    asm volatile("cp.async.commit_group;" ::: "memory");

    int sidx = 0, lidx = 2;
#pragma unroll 1
    for (int i = 0; i < NCH; i++) {
        asm volatile("cp.async.wait_group 1;" ::: "memory");
        __syncthreads();
        if (i + 2 < NCH) load_chunk(i + 2, lidx);
        asm volatile("cp.async.commit_group;" ::: "memory");

        uint32_t st = sb + sidx * STAGE;
#pragma unroll
        for (int kk = 0; kk < 2; kk++) {
            uint32_t ko = kk * 32;
            uint32_t ah[2][4], al[2][4];
            ldsm4(ah[0], st + AH_OFF + a_off + ko);
            ldsm4(ah[1], st + AH_OFF + a_off + ko + 16 * PITCH);
            ldsm4(al[0], st + AL_OFF + a_off + ko);
            ldsm4(al[1], st + AL_OFF + a_off + ko + 16 * PITCH);
#pragma unroll
            for (int np = 0; np < 4; np++) {
                uint32_t bh[4], bl[4];
                ldsm4(bh, st + BH_OFF + b_off + ko + np * 16 * PITCH);
                ldsm4(bl, st + BL_OFF + b_off + ko + np * 16 * PITCH);
#pragma unroll
                for (int mi = 0; mi < 2; mi++)
#pragma unroll
                    for (int j = 0; j < 2; j++) {
                        int ni = np * 2 + j;
                        mma_bf16(d[mi][ni], ah[mi], &bh[j*2]);
                        mma_bf16(d[mi][ni], ah[mi], &bl[j*2]);
                        mma_bf16(d[mi][ni], al[mi], &bh[j*2]);
                    }
            }
        }
        sidx = (sidx == NSTG-1) ? 0 : sidx + 1;
        lidx = (lidx == NSTG-1) ? 0 : lidx + 1;
    }

    // ---------------- epilogue ----------------
    if (PHASE == 0) {
        // warp's 64 cols = [32 gate | 32 up]; fused SwiGLU -> h hi/lo
        int icb = blockIdx.y * 128 + (warp_n >> 1);   // inter col base
#pragma unroll
        for (int mi = 0; mi < 2; mi++) {
            int rA = warp_m + mi * 16 + (lid >> 2);
            int rB = rA + 8;
            bool vA = (m0 + rA) < cnt;
            bool vB = (m0 + rB) < cnt;
            size_t rowA = (size_t)(off_e + m0 + rA);
            size_t rowB = (size_t)(off_e + m0 + rB);
#pragma unroll
            for (int ni = 0; ni < 4; ni++) {
                int col = icb + ni * 8 + (lid & 3) * 2;
                const float* g = d[mi][ni];
                const float* u = d[mi][ni + 4];
                if (vA) {
                    float h0 = g[0] / (1.f + expf(-g[0])) * u[0];
                    float h1 = g[1] / (1.f + expf(-g[1])) * u[1];
                    __nv_bfloat16 a,bb,c,dd;
                    f2bf2(h0, a, c); f2bf2(h1, bb, dd);
                    __nv_bfloat162 vh; vh.x = a;  vh.y = bb;
                    __nv_bfloat162 vl; vl.x = c;  vl.y = dd;
                    *(__nv_bfloat162*)(g_h_hi + rowA * INTER + col) = vh;
                    *(__nv_bfloat162*)(g_h_lo + rowA * INTER + col) = vl;
                }
                if (vB) {
                    float h0 = g[2] / (1.f + expf(-g[2])) * u[2];
                    float h1 = g[3] / (1.f + expf(-g[3])) * u[3];
                    __nv_bfloat16 a,bb,c,dd;
                    f2bf2(h0, a, c); f2bf2(h1, bb, dd);
                    __nv_bfloat162 vh; vh.x = a;  vh.y = bb;
                    __nv_bfloat162 vl; vl.x = c;  vl.y = dd;
                    *(__nv_bfloat162*)(g_h_hi + rowB * INTER + col) = vh;
                    *(__nv_bfloat162*)(g_h_lo + rowB * INTER + col) = vl;
                }
            }
        }
    } else {
#pragma unroll
        for (int mi = 0; mi < 2; mi++) {
            int rA = warp_m + mi * 16 + (lid >> 2);
            int rB = rA + 8;
            bool vA = (m0 + rA) < cnt;
            bool vB = (m0 + rB) < cnt;
            float* cA = g_ct + (size_t)(off_e + m0 + rA) * D_HID + n0 + warp_n + (lid & 3) * 2;
            float* cB = g_ct + (size_t)(off_e + m0 + rB) * D_HID + n0 + warp_n + (lid & 3) * 2;
#pragma unroll
            for (int ni = 0; ni < 8; ni++) {
                if (vA) { float2 v; v.x = d[mi][ni][0]; v.y = d[mi][ni][1];
                          *(float2*)(cA + ni * 8) = v; }
                if (vB) { float2 v; v.x = d[mi][ni][2]; v.y = d[mi][ni][3];
                          *(float2*)(cB + ni * 8) = v; }
            }
        }
    }
}

// ---------------- combine ----------------
__global__ void combine_kernel(float* __restrict__ out, int total4) {
    int i = blockIdx.x * blockDim.x + threadIdx.x;
    if (i >= total4) return;
    int c = i % (D_HID/4);
    int t = i / (D_HID/4);
    float w0 = g_wt[2*t], w1 = g_wt[2*t+1];
    int s0 = g_p2s[2*t], s1 = g_p2s[2*t+1];
    float4 c0 = ((const float4*)(g_ct + (size_t)s0 * D_HID))[c];
    float4 c1 = ((const float4*)(g_ct + (size_t)s1 * D_HID))[c];
    float4 o;
    o.x = fmaf(w0, c0.x, w1 * c1.x);
    o.y = fmaf(w0, c0.y, w1 * c1.y);
    o.z = fmaf(w0, c0.z, w1 * c1.z);
    o.w = fmaf(w0, c0.w, w1 * c1.w);
    ((float4*)out)[i] = o;
}

// ---------------- launch ----------------
extern "C" void kernel_launch(void* const* d_in, const int* in_sizes, int n_in,
                              void* d_out, int out_size) {
    const float* x   = (const float*)d_in[0];
    const float* rw  = (const float*)d_in[1];
    const float* gup = (const float*)d_in[2];
    const float* dwn = (const float*)d_in[3];
    float* out = (float*)d_out;
    int T = in_sizes[0] / D_HID;   // 4096

    cudaFuncSetAttribute(moe_gemm_kernel<0>, cudaFuncAttributeMaxDynamicSharedMemorySize, GEMM_SMEM);
    cudaFuncSetAttribute(moe_gemm_kernel<1>, cudaFuncAttributeMaxDynamicSharedMemorySize, GEMM_SMEM);

    zero_counts_kernel<<<1, 32>>>();                       // 0
    router_kernel<<<T, 256>>>(x, rw);                      // 1
    int prep_blocks = TPAIR + NEXP * NGU + NEXP * D_HID;   // 47104
    prep_kernel<<<prep_blocks, 128>>>(x, gup, dwn);        // 2

    dim3 g0(32, NGU / 256, NEXP);                          // 3  (GEMM1 @ index 3)
    moe_gemm_kernel<0><<<g0, 512, GEMM_SMEM>>>();

    dim3 g1(32, D_HID / 256, NEXP);                        // 4
    moe_gemm_kernel<1><<<g1, 512, GEMM_SMEM>>>();

    combine_kernel<<<(T * (D_HID/4) + 255) / 256, 256>>>(out, T * (D_HID/4)); // 5
}